// round 13
// baseline (speedup 1.0000x reference)
#include <cuda_runtime.h>
#include <cuda_bf16.h>
#include <math.h>

// ---------------- problem constants ----------------
#define NN   100000           // nodes
#define EE   300000           // directed edges
#define ETOT 400000           // edges + self loops
#define FIN  16
#define DD   128
#define HH   8
#define CC   16
#define LL   4
#define GG   1600
#define BN_EPS 1e-5f
#define NEG_SLOPE 0.2f

// ---------------- device scratch (no allocs allowed) ----------------
__device__ __align__(16) float d_h  [NN * DD];   // layer input / BN output
__device__ __align__(16) float d_xh [NN * DD];   // GAT linear output
__device__ __align__(16) float d_acc[NN * DD];   // attention aggregation accumulator
__device__ float    d_as [NN * HH];   // per-node att_src dots
__device__ float    d_ad [NN * HH];   // per-node att_dst dots
__device__ unsigned d_mx [NN * HH];   // segment max (flipped-float encoding)
__device__ float    d_den[NN * HH];   // softmax denominators
__device__ double   d_sum[DD];        // BN sum
__device__ double   d_sq [DD];        // BN sum of squares
__device__ __align__(16) float d_pool[GG * DD];  // graph pooled sums
__device__ float    d_cnt [GG];       // nodes per graph

// ---------------- helpers ----------------
__device__ __forceinline__ unsigned flip_f(float f) {
    unsigned u = __float_as_uint(f);
    return (u & 0x80000000u) ? ~u : (u | 0x80000000u);
}
__device__ __forceinline__ float unflip_f(unsigned u) {
    u = (u & 0x80000000u) ? (u ^ 0x80000000u) : ~u;
    return __uint_as_float(u);
}
__device__ __forceinline__ float lrelu(float v) {
    return v > 0.f ? v : NEG_SLOPE * v;
}
// vector reduction atomic (sm_90+): red.global.add.v4.f32
__device__ __forceinline__ void red_add_v4(float* addr, float a, float b, float c, float d) {
    asm volatile("red.global.add.v4.f32 [%0], {%1, %2, %3, %4};"
                 :: "l"(addr), "f"(a), "f"(b), "f"(c), "f"(d) : "memory");
}

// ---------------- kernels ----------------

// h = relu(x @ Wp + bp)
__global__ void k_proj(const float* __restrict__ x,
                       const float* __restrict__ Wp,
                       const float* __restrict__ bp) {
    __shared__ float sW[FIN * DD];
    int d = threadIdx.x;  // 128 threads
    for (int i = d; i < FIN * DD; i += DD) sW[i] = Wp[i];
    float b = bp[d];
    __syncthreads();
    for (int n = blockIdx.x; n < NN; n += gridDim.x) {
        const float* xr = x + (size_t)n * FIN;
        float acc = b;
#pragma unroll
        for (int f = 0; f < FIN; f++)
            acc = fmaf(__ldg(xr + f), sW[f * DD + d], acc);
        d_h[n * DD + d] = fmaxf(acc, 0.f);
    }
}

// d_xh = d_h @ B  (B is [128,128] layer weight)
__global__ void __launch_bounds__(256, 4) k_gemm(const float* __restrict__ B) {
    __shared__ float As[16][132];   // [k][m], padded
    __shared__ float Bs[16][128];   // [k][n]
    int tid = threadIdx.x;
    int tx = tid & 15, ty = tid >> 4;
    int row0 = blockIdx.x * 128;
    float acc[8][8];
#pragma unroll
    for (int i = 0; i < 8; i++)
#pragma unroll
        for (int j = 0; j < 8; j++) acc[i][j] = 0.f;

    for (int k0 = 0; k0 < 128; k0 += 16) {
#pragma unroll
        for (int i = 0; i < 8; i++) {
            int idx = tid + i * 256;
            int m = idx >> 4, k = idx & 15;
            int r = row0 + m;
            As[k][m] = (r < NN) ? d_h[r * 128 + k0 + k] : 0.f;
        }
#pragma unroll
        for (int i = 0; i < 8; i++) {
            int idx = tid + i * 256;
            int k = idx >> 7, n2 = idx & 127;
            Bs[k][n2] = B[(k0 + k) * 128 + n2];
        }
        __syncthreads();
#pragma unroll
        for (int kk = 0; kk < 16; kk++) {
            float a[8], b[8];
#pragma unroll
            for (int i = 0; i < 8; i++) a[i] = As[kk][ty * 8 + i];
#pragma unroll
            for (int j = 0; j < 8; j++) b[j] = Bs[kk][tx * 8 + j];
#pragma unroll
            for (int i = 0; i < 8; i++)
#pragma unroll
                for (int j = 0; j < 8; j++)
                    acc[i][j] = fmaf(a[i], b[j], acc[i][j]);
        }
        __syncthreads();
    }
#pragma unroll
    for (int i = 0; i < 8; i++) {
        int r = row0 + ty * 8 + i;
        if (r < NN) {
            float4* cp = (float4*)&d_xh[r * 128 + tx * 8];
            float4 v0 = make_float4(acc[i][0], acc[i][1], acc[i][2], acc[i][3]);
            float4 v1 = make_float4(acc[i][4], acc[i][5], acc[i][6], acc[i][7]);
            cp[0] = v0; cp[1] = v1;
        }
    }
}

// per-node, per-head attention dots: a_src[n,h], a_dst[n,h]
__global__ void k_att_dots(const float* __restrict__ asrcW,
                           const float* __restrict__ adstW) {
    __shared__ float sa[DD], sd[DD];
    int t = threadIdx.x;  // 256 threads
    if (t < DD) { sa[t] = asrcW[t]; sd[t] = adstW[t]; }
    __syncthreads();
    for (int i = blockIdx.x * blockDim.x + t; i < NN * HH; i += gridDim.x * blockDim.x) {
        int n = i >> 3, hh = i & 7;
        const float* xr = d_xh + n * 128 + hh * 16;
        float s = 0.f, dd2 = 0.f;
#pragma unroll
        for (int c = 0; c < 16; c++) {
            float v = xr[c];
            s   = fmaf(v, sa[hh * 16 + c], s);
            dd2 = fmaf(v, sd[hh * 16 + c], dd2);
        }
        d_as[i] = s;
        d_ad[i] = dd2;
    }
}

// zero accumulators for a layer iteration
__global__ void k_init_layer() {
    int i = blockIdx.x * blockDim.x + threadIdx.x;
    int stride = gridDim.x * blockDim.x;
    for (int j = i; j < NN * DD; j += stride) d_acc[j] = 0.f;
    for (int j = i; j < NN * HH; j += stride) { d_mx[j] = 0x007FFFFFu; d_den[j] = 0.f; }
    if (i < DD) { d_sum[i] = 0.0; d_sq[i] = 0.0; }
}

// pass 1: segment max of leaky_relu(a_src[src]+a_dst[dst]) per dst per head
__global__ void k_edge_max(const int* __restrict__ ei) {
    int e = blockIdx.x * blockDim.x + threadIdx.x;
    if (e >= ETOT) return;
    int s, dt;
    if (e < EE) { s = __ldg(ei + e); dt = __ldg(ei + EE + e); }
    else        { s = e - EE; dt = s; }
#pragma unroll
    for (int hh = 0; hh < HH; hh++) {
        float v = lrelu(d_as[s * 8 + hh] + d_ad[dt * 8 + hh]);
        atomicMax(&d_mx[dt * 8 + hh], flip_f(v));
    }
}

// pass 2: softmax denominators
__global__ void k_edge_den(const int* __restrict__ ei) {
    int e = blockIdx.x * blockDim.x + threadIdx.x;
    if (e >= ETOT) return;
    int s, dt;
    if (e < EE) { s = __ldg(ei + e); dt = __ldg(ei + EE + e); }
    else        { s = e - EE; dt = s; }
#pragma unroll
    for (int hh = 0; hh < HH; hh++) {
        float v = lrelu(d_as[s * 8 + hh] + d_ad[dt * 8 + hh]);
        float m = unflip_f(d_mx[dt * 8 + hh]);
        atomicAdd(&d_den[dt * 8 + hh], expf(v - m));
    }
}

// pass 3: weighted aggregation; one warp per edge (4 lanes per head, float4 each)
__global__ void k_edge_agg(const int* __restrict__ ei) {
    long long gt = (long long)blockIdx.x * blockDim.x + threadIdx.x;
    int e = (int)(gt >> 5);
    if (e >= ETOT) return;
    int lane = (int)(gt & 31);
    int hh = lane >> 2, q = lane & 3;
    int s, dt;
    if (e < EE) { s = __ldg(ei + e); dt = __ldg(ei + EE + e); }
    else        { s = e - EE; dt = s; }
    float v = lrelu(__ldg(&d_as[s * 8 + hh]) + __ldg(&d_ad[dt * 8 + hh]));
    float m = unflip_f(d_mx[dt * 8 + hh]);
    float den = d_den[dt * 8 + hh];
    float alpha = expf(v - m) / den;
    const float4 xv = *(const float4*)&d_xh[s * 128 + hh * 16 + q * 4];
    red_add_v4(&d_acc[dt * 128 + hh * 16 + q * 4],
               alpha * xv.x, alpha * xv.y, alpha * xv.z, alpha * xv.w);
}

// BN statistics: per-channel sum and sumsq over all nodes (double accumulate)
__global__ void k_bnstats() {
    int d = threadIdx.x;  // 128 threads
    double s = 0.0, s2 = 0.0;
    for (int r = blockIdx.x; r < NN; r += gridDim.x) {
        float v = d_acc[r * 128 + d];
        s += (double)v;
        s2 += (double)v * (double)v;
    }
    atomicAdd(&d_sum[d], s);
    atomicAdd(&d_sq[d], s2);
}

// BN normalize + affine + relu -> d_h  (GAT bias cancels under BN, skipped)
__global__ void k_bnapply(const float* __restrict__ gamma,
                          const float* __restrict__ beta) {
    int d = threadIdx.x;  // 128 threads
    double mu_d = d_sum[d] / (double)NN;
    double var_d = d_sq[d] / (double)NN - mu_d * mu_d;
    float sc = gamma[d] * rsqrtf((float)var_d + BN_EPS);
    float sh = beta[d] - (float)mu_d * sc;
    for (int r = blockIdx.x; r < NN; r += gridDim.x) {
        float v = d_acc[r * 128 + d];
        d_h[r * 128 + d] = fmaxf(fmaf(v, sc, sh), 0.f);
    }
}

// zero pooled buffers
__global__ void k_pool_init() {
    int i = blockIdx.x * blockDim.x + threadIdx.x;
    int stride = gridDim.x * blockDim.x;
    for (int j = i; j < GG * DD; j += stride) d_pool[j] = 0.f;
    for (int j = i; j < GG; j += stride) d_cnt[j] = 0.f;
}

// scatter nodes into per-graph sums
__global__ void k_pool(const int* __restrict__ batch) {
    int i = blockIdx.x * blockDim.x + threadIdx.x;
    if (i >= NN * 32) return;
    int n = i >> 5, q = i & 31;
    int g = __ldg(batch + n);
    const float4 v = *(const float4*)&d_h[n * 128 + q * 4];
    red_add_v4(&d_pool[g * 128 + q * 4], v.x, v.y, v.z, v.w);
    if (q == 0) atomicAdd(&d_cnt[g], 1.0f);
}

// output heads: relu(pooled @ W1 + b1) @ W2 + b2, per graph, 3 heads
__global__ void k_heads(const float* __restrict__ hW1, const float* __restrict__ hb1,
                        const float* __restrict__ hW2, const float* __restrict__ hb2,
                        float* __restrict__ outp) {
    int g = blockIdx.x;
    __shared__ float p[DD];
    __shared__ float red[2];
    int t = threadIdx.x;  // 64 threads
    float cnt = fmaxf(d_cnt[g], 1.0f);
    p[t]      = d_pool[g * 128 + t] / cnt;
    p[t + 64] = d_pool[g * 128 + 64 + t] / cnt;
    __syncthreads();
    for (int k = 0; k < 3; k++) {
        const float* W1 = hW1 + k * 128 * 64;
        float acc = hb1[k * 64 + t];
#pragma unroll 8
        for (int d2 = 0; d2 < 128; d2++)
            acc = fmaf(p[d2], W1[d2 * 64 + t], acc);
        acc = fmaxf(acc, 0.f) * hW2[k * 64 + t];
#pragma unroll
        for (int off = 16; off; off >>= 1)
            acc += __shfl_down_sync(0xffffffffu, acc, off);
        if ((t & 31) == 0) red[t >> 5] = acc;
        __syncthreads();
        if (t == 0) outp[g * 3 + k] = red[0] + red[1] + hb2[k];
        __syncthreads();
    }
}

// ---------------- launch ----------------
extern "C" void kernel_launch(void* const* d_in, const int* in_sizes, int n_in,
                              void* d_out, int out_size) {
    const float* x     = (const float*)d_in[0];
    const int*   ei    = (const int*)d_in[1];    // jax x64 disabled -> int32
    const int*   batch = (const int*)d_in[2];    // int32
    const float* Wp    = (const float*)d_in[3];
    const float* bp    = (const float*)d_in[4];
    const float* Wg    = (const float*)d_in[5];
    const float* asrc  = (const float*)d_in[6];
    const float* adst  = (const float*)d_in[7];
    // d_in[8] = bg : GAT bias, exactly cancelled by the following BatchNorm
    const float* gamma = (const float*)d_in[9];
    const float* beta  = (const float*)d_in[10];
    const float* hW1   = (const float*)d_in[11];
    const float* hb1   = (const float*)d_in[12];
    const float* hW2   = (const float*)d_in[13];
    const float* hb2   = (const float*)d_in[14];
    float*       outp  = (float*)d_out;

    const int gemm_blocks = (NN + 127) / 128;          // 782
    const int edge_blocks = (ETOT + 255) / 256;        // 1563
    const int agg_blocks  = (ETOT * 32 + 255) / 256;   // 50000
    const int pool_blocks = (NN * 32 + 255) / 256;     // 12500

    k_proj<<<2048, 128>>>(x, Wp, bp);

    for (int l = 0; l < LL; l++) {
        const float* B = Wg + (size_t)l * DD * DD;
        k_init_layer<<<4096, 256>>>();
        k_gemm<<<gemm_blocks, 256>>>(B);
        k_att_dots<<<1024, 256>>>(asrc + l * HH * CC, adst + l * HH * CC);
        k_edge_max<<<edge_blocks, 256>>>(ei);
        k_edge_den<<<edge_blocks, 256>>>(ei);
        k_edge_agg<<<agg_blocks, 256>>>(ei);
        k_bnstats<<<512, 128>>>();
        k_bnapply<<<1024, 128>>>(gamma + l * DD, beta + l * DD);
    }

    k_pool_init<<<512, 256>>>();
    k_pool<<<pool_blocks, 256>>>(batch);
    k_heads<<<GG, 64>>>(hW1, hb1, hW2, hb2, outp);
}

// round 14
// speedup vs baseline: 3.6122x; 3.6122x over previous
#include <cuda_runtime.h>
#include <cuda_bf16.h>
#include <math.h>

// ---------------- problem constants ----------------
#define NN   100000           // nodes
#define EE   300000           // directed edges
#define ETOT 400000           // edges + self loops
#define FIN  16
#define DD   128
#define HH   8
#define CC   16
#define LL   4
#define GG   1600
#define BN_EPS 1e-5f
#define NEG_SLOPE 0.2f

// ---------------- device scratch (no allocs allowed) ----------------
__device__ __align__(16) float d_h  [NN * DD];   // layer input / BN output
__device__ __align__(16) float d_xh [NN * DD];   // GAT linear output
__device__ __align__(16) float d_acc[NN * DD];   // attention aggregation accumulator (unnormalized)
__device__ float    d_as [NN * HH];   // per-node att_src dots
__device__ float    d_ad [NN * HH];   // per-node att_dst dots
__device__ unsigned d_mx [NN * HH];   // segment max (flipped-float encoding)
__device__ float    d_den[NN * HH];   // softmax denominators -> reciprocals after k_inv
__device__ double   d_sum[DD];        // BN sum
__device__ double   d_sq [DD];        // BN sum of squares
__device__ __align__(16) float d_pool[GG * DD];  // graph pooled sums
__device__ float    d_cnt [GG];       // nodes per graph

// ---------------- helpers ----------------
__device__ __forceinline__ unsigned flip_f(float f) {
    unsigned u = __float_as_uint(f);
    return (u & 0x80000000u) ? ~u : (u | 0x80000000u);
}
__device__ __forceinline__ float unflip_f(unsigned u) {
    u = (u & 0x80000000u) ? (u ^ 0x80000000u) : ~u;
    return __uint_as_float(u);
}
__device__ __forceinline__ float lrelu(float v) {
    return v > 0.f ? v : NEG_SLOPE * v;
}
// vector reduction atomic (sm_90+): red.global.add.v4.f32
__device__ __forceinline__ void red_add_v4(float* addr, float a, float b, float c, float d) {
    asm volatile("red.global.add.v4.f32 [%0], {%1, %2, %3, %4};"
                 :: "l"(addr), "f"(a), "f"(b), "f"(c), "f"(d) : "memory");
}

// ---------------- kernels ----------------

// h = relu(x @ Wp + bp)
__global__ void k_proj(const float* __restrict__ x,
                       const float* __restrict__ Wp,
                       const float* __restrict__ bp) {
    __shared__ float sW[FIN * DD];
    int d = threadIdx.x;  // 128 threads
    for (int i = d; i < FIN * DD; i += DD) sW[i] = Wp[i];
    float b = bp[d];
    __syncthreads();
    for (int n = blockIdx.x; n < NN; n += gridDim.x) {
        const float* xr = x + (size_t)n * FIN;
        float acc = b;
#pragma unroll
        for (int f = 0; f < FIN; f++)
            acc = fmaf(__ldg(xr + f), sW[f * DD + d], acc);
        d_h[n * DD + d] = fmaxf(acc, 0.f);
    }
}

// d_xh = d_h @ B ; fused per-head attention dots into the epilogue.
// 128x128 C-tile, 256 threads, 8x8 register blocking.
__global__ void __launch_bounds__(256, 2) k_gemm(const float* __restrict__ B,
                                                 const float* __restrict__ asrcW,
                                                 const float* __restrict__ adstW) {
    __shared__ float As[16][132];   // [k][m], padded
    __shared__ float Bs[16][128];   // [k][n]
    __shared__ float sa[DD], sd[DD];
    int tid = threadIdx.x;
    int tx = tid & 15, ty = tid >> 4;
    if (tid < DD) sa[tid] = asrcW[tid];
    else          sd[tid - DD] = adstW[tid - DD];
    int row0 = blockIdx.x * 128;
    float acc[8][8];
#pragma unroll
    for (int i = 0; i < 8; i++)
#pragma unroll
        for (int j = 0; j < 8; j++) acc[i][j] = 0.f;

    for (int k0 = 0; k0 < 128; k0 += 16) {
#pragma unroll
        for (int i = 0; i < 8; i++) {
            int idx = tid + i * 256;
            int m = idx >> 4, k = idx & 15;
            int r = row0 + m;
            As[k][m] = (r < NN) ? d_h[r * 128 + k0 + k] : 0.f;
        }
#pragma unroll
        for (int i = 0; i < 8; i++) {
            int idx = tid + i * 256;
            int k = idx >> 7, n2 = idx & 127;
            Bs[k][n2] = B[(k0 + k) * 128 + n2];
        }
        __syncthreads();
#pragma unroll
        for (int kk = 0; kk < 16; kk++) {
            float a[8], b[8];
#pragma unroll
            for (int i = 0; i < 8; i++) a[i] = As[kk][ty * 8 + i];
#pragma unroll
            for (int j = 0; j < 8; j++) b[j] = Bs[kk][tx * 8 + j];
#pragma unroll
            for (int i = 0; i < 8; i++)
#pragma unroll
                for (int j = 0; j < 8; j++)
                    acc[i][j] = fmaf(a[i], b[j], acc[i][j]);
        }
        __syncthreads();
    }

    // epilogue: write xh + fused attention dots
    int head = tx >> 1;            // 8 cols per thread => half a head
    int off  = head * 16 + (tx & 1) * 8;
#pragma unroll
    for (int i = 0; i < 8; i++) {
        int r = row0 + ty * 8 + i;
        float s = 0.f, dd2 = 0.f;
#pragma unroll
        for (int j = 0; j < 8; j++) {
            s   = fmaf(acc[i][j], sa[off + j], s);
            dd2 = fmaf(acc[i][j], sd[off + j], dd2);
        }
        s   += __shfl_xor_sync(0xffffffffu, s, 1);
        dd2 += __shfl_xor_sync(0xffffffffu, dd2, 1);
        if (r < NN) {
            float4* cp = (float4*)&d_xh[r * 128 + tx * 8];
            cp[0] = make_float4(acc[i][0], acc[i][1], acc[i][2], acc[i][3]);
            cp[1] = make_float4(acc[i][4], acc[i][5], acc[i][6], acc[i][7]);
            if ((tx & 1) == 0) {
                d_as[r * 8 + head] = s;
                d_ad[r * 8 + head] = dd2;
            }
        }
    }
}

// zero accumulators for a layer iteration
__global__ void k_init_layer() {
    int i = blockIdx.x * blockDim.x + threadIdx.x;
    int stride = gridDim.x * blockDim.x;
    float4 z = make_float4(0.f, 0.f, 0.f, 0.f);
    for (int j = i; j < NN * DD / 4; j += stride) ((float4*)d_acc)[j] = z;
    for (int j = i; j < NN * HH; j += stride) { d_mx[j] = 0x007FFFFFu; d_den[j] = 0.f; }
    if (i < DD) { d_sum[i] = 0.0; d_sq[i] = 0.0; }
}

// pass 1: segment max per (dst, head). 8 threads per edge (one head each).
__global__ void k_edge_max(const int* __restrict__ ei) {
    int t = blockIdx.x * blockDim.x + threadIdx.x;
    int e = t >> 3, hh = t & 7;
    if (e >= ETOT) return;
    int s, dt;
    if (e < EE) { s = __ldg(ei + e); dt = __ldg(ei + EE + e); }
    else        { s = e - EE; dt = s; }
    float v = lrelu(__ldg(&d_as[s * 8 + hh]) + __ldg(&d_ad[dt * 8 + hh]));
    atomicMax(&d_mx[dt * 8 + hh], flip_f(v));
}

// pass 2 (fused den + aggregation): one warp per edge.
// lanes: 4 per head; accumulate exp(e-m)*x_src into d_acc and exp(e-m) into d_den.
__global__ void k_edge_agg(const int* __restrict__ ei) {
    long long gt = (long long)blockIdx.x * blockDim.x + threadIdx.x;
    int e = (int)(gt >> 5);
    if (e >= ETOT) return;
    int lane = (int)(gt & 31);
    int hh = lane >> 2, q = lane & 3;
    int s, dt;
    if (e < EE) { s = __ldg(ei + e); dt = __ldg(ei + EE + e); }
    else        { s = e - EE; dt = s; }
    float v = lrelu(__ldg(&d_as[s * 8 + hh]) + __ldg(&d_ad[dt * 8 + hh]));
    float m = unflip_f(d_mx[dt * 8 + hh]);
    float ex = __expf(v - m);
    if (q == 0) atomicAdd(&d_den[dt * 8 + hh], ex);
    const float4 xv = *(const float4*)&d_xh[s * 128 + hh * 16 + q * 4];
    red_add_v4(&d_acc[dt * 128 + hh * 16 + q * 4],
               ex * xv.x, ex * xv.y, ex * xv.z, ex * xv.w);
}

// reciprocal of denominators (exact div, done once)
__global__ void k_inv() {
    int i = blockIdx.x * blockDim.x + threadIdx.x;
    if (i < NN * HH) d_den[i] = 1.0f / d_den[i];
}

// BN statistics over normalized values (float partials, double combine)
__global__ void k_bnstats() {
    int d = threadIdx.x;  // 128 threads
    int hh = d >> 4;
    float s = 0.f, s2 = 0.f;
    for (int r = blockIdx.x; r < NN; r += gridDim.x) {
        float v = d_acc[r * 128 + d] * d_den[r * 8 + hh];
        s += v;
        s2 = fmaf(v, v, s2);
    }
    atomicAdd(&d_sum[d], (double)s);
    atomicAdd(&d_sq[d], (double)s2);
}

// BN normalize + affine + relu -> d_h  (GAT bias cancels under BN, skipped)
__global__ void k_bnapply(const float* __restrict__ gamma,
                          const float* __restrict__ beta) {
    int d = threadIdx.x;  // 128 threads
    int hh = d >> 4;
    double mu_d = d_sum[d] / (double)NN;
    double var_d = d_sq[d] / (double)NN - mu_d * mu_d;
    float sc = gamma[d] * rsqrtf((float)var_d + BN_EPS);
    float sh = beta[d] - (float)mu_d * sc;
    for (int r = blockIdx.x; r < NN; r += gridDim.x) {
        float v = d_acc[r * 128 + d] * d_den[r * 8 + hh];
        d_h[r * 128 + d] = fmaxf(fmaf(v, sc, sh), 0.f);
    }
}

// zero pooled buffers
__global__ void k_pool_init() {
    int i = blockIdx.x * blockDim.x + threadIdx.x;
    int stride = gridDim.x * blockDim.x;
    for (int j = i; j < GG * DD; j += stride) d_pool[j] = 0.f;
    for (int j = i; j < GG; j += stride) d_cnt[j] = 0.f;
}

// scatter nodes into per-graph sums
__global__ void k_pool(const int* __restrict__ batch) {
    int i = blockIdx.x * blockDim.x + threadIdx.x;
    if (i >= NN * 32) return;
    int n = i >> 5, q = i & 31;
    int g = __ldg(batch + n);
    const float4 v = *(const float4*)&d_h[n * 128 + q * 4];
    red_add_v4(&d_pool[g * 128 + q * 4], v.x, v.y, v.z, v.w);
    if (q == 0) atomicAdd(&d_cnt[g], 1.0f);
}

// output heads: relu(pooled @ W1 + b1) @ W2 + b2, per graph, 3 heads
__global__ void k_heads(const float* __restrict__ hW1, const float* __restrict__ hb1,
                        const float* __restrict__ hW2, const float* __restrict__ hb2,
                        float* __restrict__ outp) {
    int g = blockIdx.x;
    __shared__ float p[DD];
    __shared__ float red[2];
    int t = threadIdx.x;  // 64 threads
    float cnt = fmaxf(d_cnt[g], 1.0f);
    p[t]      = d_pool[g * 128 + t] / cnt;
    p[t + 64] = d_pool[g * 128 + 64 + t] / cnt;
    __syncthreads();
    for (int k = 0; k < 3; k++) {
        const float* W1 = hW1 + k * 128 * 64;
        float acc = hb1[k * 64 + t];
#pragma unroll 8
        for (int d2 = 0; d2 < 128; d2++)
            acc = fmaf(p[d2], W1[d2 * 64 + t], acc);
        acc = fmaxf(acc, 0.f) * hW2[k * 64 + t];
#pragma unroll
        for (int off = 16; off; off >>= 1)
            acc += __shfl_down_sync(0xffffffffu, acc, off);
        if ((t & 31) == 0) red[t >> 5] = acc;
        __syncthreads();
        if (t == 0) outp[g * 3 + k] = red[0] + red[1] + hb2[k];
        __syncthreads();
    }
}

// ---------------- launch ----------------
extern "C" void kernel_launch(void* const* d_in, const int* in_sizes, int n_in,
                              void* d_out, int out_size) {
    const float* x     = (const float*)d_in[0];
    const int*   ei    = (const int*)d_in[1];    // jax x64 disabled -> int32
    const int*   batch = (const int*)d_in[2];    // int32
    const float* Wp    = (const float*)d_in[3];
    const float* bp    = (const float*)d_in[4];
    const float* Wg    = (const float*)d_in[5];
    const float* asrc  = (const float*)d_in[6];
    const float* adst  = (const float*)d_in[7];
    // d_in[8] = bg : GAT bias, exactly cancelled by the following BatchNorm
    const float* gamma = (const float*)d_in[9];
    const float* beta  = (const float*)d_in[10];
    const float* hW1   = (const float*)d_in[11];
    const float* hb1   = (const float*)d_in[12];
    const float* hW2   = (const float*)d_in[13];
    const float* hb2   = (const float*)d_in[14];
    float*       outp  = (float*)d_out;

    const int gemm_blocks = (NN + 127) / 128;            // 782
    const int max_blocks  = (ETOT * 8 + 255) / 256;      // 12500
    const int agg_blocks  = (ETOT * 32 + 255) / 256;     // 50000
    const int pool_blocks = (NN * 32 + 255) / 256;       // 12500

    k_proj<<<2048, 128>>>(x, Wp, bp);

    for (int l = 0; l < LL; l++) {
        const float* B = Wg + (size_t)l * DD * DD;
        k_init_layer<<<2048, 256>>>();
        k_gemm<<<gemm_blocks, 256>>>(B, asrc + l * HH * CC, adst + l * HH * CC);
        k_edge_max<<<max_blocks, 256>>>(ei);
        k_edge_agg<<<agg_blocks, 256>>>(ei);
        k_inv<<<(NN * HH + 255) / 256, 256>>>();
        k_bnstats<<<1024, 128>>>();
        k_bnapply<<<2048, 128>>>(gamma + l * DD, beta + l * DD);
    }

    k_pool_init<<<512, 256>>>();
    k_pool<<<pool_blocks, 256>>>(batch);
    k_heads<<<GG, 64>>>(hW1, hb1, hW2, hb2, outp);
}

// round 15
// speedup vs baseline: 4.0995x; 1.1349x over previous
#include <cuda_runtime.h>
#include <cuda_bf16.h>
#include <math.h>

// ---------------- problem constants ----------------
#define NN   100000           // nodes
#define EE   300000           // directed edges
#define FIN  16
#define DD   128
#define HH   8
#define CC   16
#define LL   4
#define GG   1600
#define BN_EPS 1e-5f
#define NEG_SLOPE 0.2f

// ---------------- device scratch (no allocs allowed) ----------------
__device__ __align__(16) float d_h  [NN * DD];   // proj output (layer-0 GEMM input)
__device__ __align__(16) float d_xh [NN * DD];   // GAT linear output
__device__ __align__(16) float d_acc[NN * DD];   // softmax-normalized aggregation (pre-BN)
__device__ float  d_as [NN * HH];   // per-node att_src dots
__device__ float  d_ad [NN * HH];   // per-node att_dst dots
__device__ double d_sum[DD];        // BN sum
__device__ double d_sq [DD];        // BN sum of squares
__device__ float  d_bnsc[DD];       // BN scale  (gamma / sqrt(var+eps))
__device__ float  d_bnsh[DD];       // BN shift  (beta - mu*scale)
__device__ __align__(16) float d_pool[GG * DD];  // graph pooled sums
__device__ float  d_cnt [GG];       // nodes per graph
// CSR (dst-indexed, real edges only; self loops handled analytically)
__device__ int d_deg[NN];
__device__ int d_rowptr[NN + 1];
__device__ int d_wp[NN];
__device__ int d_col[EE];

// ---------------- helpers ----------------
__device__ __forceinline__ float lrelu(float v) {
    return v > 0.f ? v : NEG_SLOPE * v;
}
__device__ __forceinline__ void red_add_v4(float* addr, float a, float b, float c, float d) {
    asm volatile("red.global.add.v4.f32 [%0], {%1, %2, %3, %4};"
                 :: "l"(addr), "f"(a), "f"(b), "f"(c), "f"(d) : "memory");
}

// ---------------- CSR build (once per call) ----------------
__global__ void k_zero() {
    int i = blockIdx.x * blockDim.x + threadIdx.x;
    int st = gridDim.x * blockDim.x;
    for (int j = i; j < NN; j += st) d_deg[j] = 0;
    for (int j = i; j < GG * DD; j += st) d_pool[j] = 0.f;
    for (int j = i; j < GG; j += st) d_cnt[j] = 0.f;
    if (i < DD) { d_sum[i] = 0.0; d_sq[i] = 0.0; }
}

__global__ void k_hist(const int* __restrict__ ei) {
    int e = blockIdx.x * blockDim.x + threadIdx.x;
    if (e < EE) atomicAdd(&d_deg[__ldg(ei + EE + e)], 1);
}

// single-block exclusive scan over degrees -> rowptr and write-pointers
__global__ void k_scan() {
    __shared__ int part[1024];
    const int T = 1024;
    const int CH = (NN + T - 1) / T;     // 98
    int t = threadIdx.x;
    int b = t * CH;
    int e = min(b + CH, NN);
    int s = 0;
    for (int i = b; i < e; i++) s += d_deg[i];
    part[t] = s;
    __syncthreads();
    // Hillis-Steele inclusive scan
    for (int off = 1; off < T; off <<= 1) {
        int tmp = (t >= off) ? part[t - off] : 0;
        __syncthreads();
        part[t] += tmp;
        __syncthreads();
    }
    int run = part[t] - s;               // exclusive prefix
    for (int i = b; i < e; i++) {
        d_rowptr[i] = run;
        d_wp[i] = run;
        run += d_deg[i];
    }
    if (t == T - 1) d_rowptr[NN] = run;  // == EE
}

__global__ void k_fill(const int* __restrict__ ei) {
    int e = blockIdx.x * blockDim.x + threadIdx.x;
    if (e >= EE) return;
    int s = __ldg(ei + e), dt = __ldg(ei + EE + e);
    int p = atomicAdd(&d_wp[dt], 1);
    d_col[p] = s;
}

// ---------------- compute kernels ----------------

// h = relu(x @ Wp + bp)
__global__ void k_proj(const float* __restrict__ x,
                       const float* __restrict__ Wp,
                       const float* __restrict__ bp) {
    __shared__ float sW[FIN * DD];
    int d = threadIdx.x;  // 128 threads
    for (int i = d; i < FIN * DD; i += DD) sW[i] = Wp[i];
    float b = bp[d];
    __syncthreads();
    for (int n = blockIdx.x; n < NN; n += gridDim.x) {
        const float* xr = x + (size_t)n * FIN;
        float acc = b;
#pragma unroll
        for (int f = 0; f < FIN; f++)
            acc = fmaf(__ldg(xr + f), sW[f * DD + d], acc);
        d_h[n * DD + d] = fmaxf(acc, 0.f);
    }
}

// xh = A @ B where A = (fused ? relu(BN(d_acc)) : d_h). Epilogue fuses att dots.
// 128x128 C-tile, 256 threads, 8x8 register blocking.
__global__ void __launch_bounds__(256, 2) k_gemm(const float* __restrict__ B,
                                                 const float* __restrict__ asrcW,
                                                 const float* __restrict__ adstW,
                                                 int fused) {
    __shared__ float As[16][132];   // [k][m], padded
    __shared__ float Bs[16][128];   // [k][n]
    __shared__ float sa[DD], sd[DD], ssc[DD], ssh[DD];
    int tid = threadIdx.x;
    int tx = tid & 15, ty = tid >> 4;
    if (tid < DD) { sa[tid] = asrcW[tid]; ssc[tid] = d_bnsc[tid]; }
    else          { sd[tid - DD] = adstW[tid - DD]; ssh[tid - DD] = d_bnsh[tid - DD]; }
    __syncthreads();
    int row0 = blockIdx.x * 128;
    float acc[8][8];
#pragma unroll
    for (int i = 0; i < 8; i++)
#pragma unroll
        for (int j = 0; j < 8; j++) acc[i][j] = 0.f;

    for (int k0 = 0; k0 < 128; k0 += 16) {
#pragma unroll
        for (int i = 0; i < 8; i++) {
            int idx = tid + i * 256;
            int m = idx >> 4, k = idx & 15;
            int r = row0 + m;
            float v = 0.f;
            if (r < NN) {
                int c = k0 + k;
                if (fused) v = fmaxf(fmaf(d_acc[r * 128 + c], ssc[c], ssh[c]), 0.f);
                else       v = d_h[r * 128 + c];
            }
            As[k][m] = v;
        }
#pragma unroll
        for (int i = 0; i < 8; i++) {
            int idx = tid + i * 256;
            int k = idx >> 7, n2 = idx & 127;
            Bs[k][n2] = B[(k0 + k) * 128 + n2];
        }
        __syncthreads();
#pragma unroll
        for (int kk = 0; kk < 16; kk++) {
            float a[8], b[8];
#pragma unroll
            for (int i = 0; i < 8; i++) a[i] = As[kk][ty * 8 + i];
#pragma unroll
            for (int j = 0; j < 8; j++) b[j] = Bs[kk][tx * 8 + j];
#pragma unroll
            for (int i = 0; i < 8; i++)
#pragma unroll
                for (int j = 0; j < 8; j++)
                    acc[i][j] = fmaf(a[i], b[j], acc[i][j]);
        }
        __syncthreads();
    }

    // epilogue: write xh + fused attention dots
    int head = tx >> 1;            // 8 cols per thread => half a head
    int off  = head * 16 + (tx & 1) * 8;
#pragma unroll
    for (int i = 0; i < 8; i++) {
        int r = row0 + ty * 8 + i;
        float s = 0.f, dd2 = 0.f;
#pragma unroll
        for (int j = 0; j < 8; j++) {
            s   = fmaf(acc[i][j], sa[off + j], s);
            dd2 = fmaf(acc[i][j], sd[off + j], dd2);
        }
        s   += __shfl_xor_sync(0xffffffffu, s, 1);
        dd2 += __shfl_xor_sync(0xffffffffu, dd2, 1);
        if (r < NN) {
            float4* cp = (float4*)&d_xh[r * 128 + tx * 8];
            cp[0] = make_float4(acc[i][0], acc[i][1], acc[i][2], acc[i][3]);
            cp[1] = make_float4(acc[i][4], acc[i][5], acc[i][6], acc[i][7]);
            if ((tx & 1) == 0) {
                d_as[r * 8 + head] = s;
                d_ad[r * 8 + head] = dd2;
            }
        }
    }
}

// Fused attention: warp per dst node. max -> exp -> den -> weighted sum ->
// normalize -> store, plus per-channel BN stat partials. No atomics on features.
__global__ void __launch_bounds__(256) k_agg() {
    __shared__ float ssum[DD], ssq[DD];
    int tid = threadIdx.x;
    if (tid < DD) { ssum[tid] = 0.f; ssq[tid] = 0.f; }
    __syncthreads();
    int lane = tid & 31;
    int h = lane >> 2;                 // head (4 lanes per head)
    int warp_g = blockIdx.x * (blockDim.x >> 5) + (tid >> 5);
    int nwarps = gridDim.x * (blockDim.x >> 5);
    float4 psum = make_float4(0.f, 0.f, 0.f, 0.f);
    float4 psq  = make_float4(0.f, 0.f, 0.f, 0.f);

    for (int n = warp_g; n < NN; n += nwarps) {
        float a_d = __ldg(&d_ad[n * 8 + h]);
        int beg = d_rowptr[n], end = d_rowptr[n + 1];
        // pass 1: max (self loop included)
        float m = lrelu(__ldg(&d_as[n * 8 + h]) + a_d);
        for (int i = beg; i < end; i++) {
            int s = __ldg(&d_col[i]);
            m = fmaxf(m, lrelu(__ldg(&d_as[s * 8 + h]) + a_d));
        }
        // pass 2: exp, denom, weighted sum
        float den;
        float4 acc;
        {
            float ex = __expf(lrelu(__ldg(&d_as[n * 8 + h]) + a_d) - m);
            den = ex;
            const float4 xv = *(const float4*)&d_xh[n * 128 + lane * 4];
            acc = make_float4(ex * xv.x, ex * xv.y, ex * xv.z, ex * xv.w);
        }
        for (int i = beg; i < end; i++) {
            int s = __ldg(&d_col[i]);
            float ex = __expf(lrelu(__ldg(&d_as[s * 8 + h]) + a_d) - m);
            den += ex;
            const float4 xv = *(const float4*)&d_xh[s * 128 + lane * 4];
            acc.x = fmaf(ex, xv.x, acc.x);
            acc.y = fmaf(ex, xv.y, acc.y);
            acc.z = fmaf(ex, xv.z, acc.z);
            acc.w = fmaf(ex, xv.w, acc.w);
        }
        float r = 1.f / den;
        float4 v = make_float4(acc.x * r, acc.y * r, acc.z * r, acc.w * r);
        *(float4*)&d_acc[n * 128 + lane * 4] = v;
        psum.x += v.x; psum.y += v.y; psum.z += v.z; psum.w += v.w;
        psq.x = fmaf(v.x, v.x, psq.x); psq.y = fmaf(v.y, v.y, psq.y);
        psq.z = fmaf(v.z, v.z, psq.z); psq.w = fmaf(v.w, v.w, psq.w);
    }
    // channel owned by lane: c = lane*4 + j (== h*16 + q*4 + j)
    int c = lane * 4;
    atomicAdd(&ssum[c + 0], psum.x); atomicAdd(&ssum[c + 1], psum.y);
    atomicAdd(&ssum[c + 2], psum.z); atomicAdd(&ssum[c + 3], psum.w);
    atomicAdd(&ssq [c + 0], psq.x);  atomicAdd(&ssq [c + 1], psq.y);
    atomicAdd(&ssq [c + 2], psq.z);  atomicAdd(&ssq [c + 3], psq.w);
    __syncthreads();
    if (tid < DD) {
        atomicAdd(&d_sum[tid], (double)ssum[tid]);
        atomicAdd(&d_sq[tid],  (double)ssq[tid]);
    }
}

// finalize BN scale/shift for this layer, reset stats for next layer
__global__ void k_bnfinal(const float* __restrict__ gamma,
                          const float* __restrict__ beta) {
    int d = threadIdx.x;  // 128 threads
    double mu = d_sum[d] / (double)NN;
    double var = d_sq[d] / (double)NN - mu * mu;
    float sc = gamma[d] * rsqrtf((float)var + BN_EPS);
    d_bnsc[d] = sc;
    d_bnsh[d] = beta[d] - (float)mu * sc;
    d_sum[d] = 0.0;
    d_sq[d] = 0.0;
}

// scatter nodes into per-graph sums, fusing the final BN+relu
__global__ void k_pool(const int* __restrict__ batch) {
    int i = blockIdx.x * blockDim.x + threadIdx.x;
    if (i >= NN * 32) return;
    int n = i >> 5, q = i & 31;
    int g = __ldg(batch + n);
    int c = q * 4;
    const float4 a = *(const float4*)&d_acc[n * 128 + c];
    float vx = fmaxf(fmaf(a.x, __ldg(&d_bnsc[c + 0]), __ldg(&d_bnsh[c + 0])), 0.f);
    float vy = fmaxf(fmaf(a.y, __ldg(&d_bnsc[c + 1]), __ldg(&d_bnsh[c + 1])), 0.f);
    float vz = fmaxf(fmaf(a.z, __ldg(&d_bnsc[c + 2]), __ldg(&d_bnsh[c + 2])), 0.f);
    float vw = fmaxf(fmaf(a.w, __ldg(&d_bnsc[c + 3]), __ldg(&d_bnsh[c + 3])), 0.f);
    red_add_v4(&d_pool[g * 128 + c], vx, vy, vz, vw);
    if (q == 0) atomicAdd(&d_cnt[g], 1.0f);
}

// output heads: relu(pooled @ W1 + b1) @ W2 + b2, per graph, 3 heads
__global__ void k_heads(const float* __restrict__ hW1, const float* __restrict__ hb1,
                        const float* __restrict__ hW2, const float* __restrict__ hb2,
                        float* __restrict__ outp) {
    int g = blockIdx.x;
    __shared__ float p[DD];
    __shared__ float red[2];
    int t = threadIdx.x;  // 64 threads
    float cnt = fmaxf(d_cnt[g], 1.0f);
    p[t]      = d_pool[g * 128 + t] / cnt;
    p[t + 64] = d_pool[g * 128 + 64 + t] / cnt;
    __syncthreads();
    for (int k = 0; k < 3; k++) {
        const float* W1 = hW1 + k * 128 * 64;
        float acc = hb1[k * 64 + t];
#pragma unroll 8
        for (int d2 = 0; d2 < 128; d2++)
            acc = fmaf(p[d2], W1[d2 * 64 + t], acc);
        acc = fmaxf(acc, 0.f) * hW2[k * 64 + t];
#pragma unroll
        for (int off = 16; off; off >>= 1)
            acc += __shfl_down_sync(0xffffffffu, acc, off);
        if ((t & 31) == 0) red[t >> 5] = acc;
        __syncthreads();
        if (t == 0) outp[g * 3 + k] = red[0] + red[1] + hb2[k];
        __syncthreads();
    }
}

// ---------------- launch ----------------
extern "C" void kernel_launch(void* const* d_in, const int* in_sizes, int n_in,
                              void* d_out, int out_size) {
    const float* x     = (const float*)d_in[0];
    const int*   ei    = (const int*)d_in[1];    // int32 (jax x64 disabled)
    const int*   batch = (const int*)d_in[2];
    const float* Wp    = (const float*)d_in[3];
    const float* bp    = (const float*)d_in[4];
    const float* Wg    = (const float*)d_in[5];
    const float* asrc  = (const float*)d_in[6];
    const float* adst  = (const float*)d_in[7];
    // d_in[8] = bg : GAT bias, exactly cancelled by the following BatchNorm
    const float* gamma = (const float*)d_in[9];
    const float* beta  = (const float*)d_in[10];
    const float* hW1   = (const float*)d_in[11];
    const float* hb1   = (const float*)d_in[12];
    const float* hW2   = (const float*)d_in[13];
    const float* hb2   = (const float*)d_in[14];
    float*       outp  = (float*)d_out;

    const int gemm_blocks = (NN + 127) / 128;        // 782
    const int e_blocks    = (EE + 255) / 256;        // 1172
    const int pool_blocks = (NN * 32 + 255) / 256;   // 12500

    // CSR build + zero init (edge list identical across layers)
    k_zero<<<512, 256>>>();
    k_hist<<<e_blocks, 256>>>(ei);
    k_scan<<<1, 1024>>>();
    k_fill<<<e_blocks, 256>>>(ei);

    k_proj<<<2048, 128>>>(x, Wp, bp);

    for (int l = 0; l < LL; l++) {
        const float* B = Wg + (size_t)l * DD * DD;
        k_gemm<<<gemm_blocks, 256>>>(B, asrc + l * HH * CC, adst + l * HH * CC, l > 0);
        k_agg<<<1024, 256>>>();
        k_bnfinal<<<1, 128>>>(gamma + l * DD, beta + l * DD);
    }

    k_pool<<<pool_blocks, 256>>>(batch);
    k_heads<<<GG, 64>>>(hW1, hb1, hW2, hb2, outp);
}

// round 16
// speedup vs baseline: 4.2380x; 1.0338x over previous
#include <cuda_runtime.h>
#include <cuda_bf16.h>
#include <math.h>

// ---------------- problem constants ----------------
#define NN   100000           // nodes
#define EE   300000           // directed edges
#define FIN  16
#define DD   128
#define HH   8
#define CC   16
#define LL   4
#define GG   1600
#define BN_EPS 1e-5f
#define NEG_SLOPE 0.2f

// ---------------- device scratch (no allocs allowed) ----------------
__device__ __align__(16) float d_h  [NN * DD];   // proj output (layer-0 GEMM input)
__device__ __align__(16) float d_xh [NN * DD];   // GAT linear output
__device__ __align__(16) float d_acc[NN * DD];   // softmax-normalized aggregation (pre-BN)
__device__ float  d_as [NN * HH];   // per-node att_src dots
__device__ float  d_ad [NN * HH];   // per-node att_dst dots
__device__ double d_sum[DD];        // BN sum
__device__ double d_sq [DD];        // BN sum of squares
__device__ float  d_bnsc[DD];       // BN scale  (gamma / sqrt(var+eps))
__device__ float  d_bnsh[DD];       // BN shift  (beta - mu*scale)
__device__ __align__(16) float d_pool[GG * DD];  // graph pooled sums
__device__ float  d_cnt [GG];       // nodes per graph
// CSR (dst-indexed, real edges only; self loops handled analytically)
__device__ int d_deg[NN];
__device__ int d_rowptr[NN + 1];
__device__ int d_wp[NN];
__device__ int d_col[EE];

// ---------------- helpers ----------------
__device__ __forceinline__ float lrelu(float v) {
    return v > 0.f ? v : NEG_SLOPE * v;
}
__device__ __forceinline__ void red_add_v4(float* addr, float a, float b, float c, float d) {
    asm volatile("red.global.add.v4.f32 [%0], {%1, %2, %3, %4};"
                 :: "l"(addr), "f"(a), "f"(b), "f"(c), "f"(d) : "memory");
}

// ---------------- CSR build (once per call) ----------------
__global__ void k_zero() {
    int i = blockIdx.x * blockDim.x + threadIdx.x;
    int st = gridDim.x * blockDim.x;
    for (int j = i; j < NN; j += st) d_deg[j] = 0;
    for (int j = i; j < GG * DD; j += st) d_pool[j] = 0.f;
    for (int j = i; j < GG; j += st) d_cnt[j] = 0.f;
    if (i < DD) { d_sum[i] = 0.0; d_sq[i] = 0.0; }
}

__global__ void k_hist(const int* __restrict__ ei) {
    int e = blockIdx.x * blockDim.x + threadIdx.x;
    if (e < EE) atomicAdd(&d_deg[__ldg(ei + EE + e)], 1);
}

// single-block exclusive scan over degrees -> rowptr and write-pointers
__global__ void k_scan() {
    __shared__ int part[1024];
    const int T = 1024;
    const int CH = (NN + T - 1) / T;     // 98
    int t = threadIdx.x;
    int b = t * CH;
    int e = min(b + CH, NN);
    int s = 0;
    for (int i = b; i < e; i++) s += d_deg[i];
    part[t] = s;
    __syncthreads();
    // Hillis-Steele inclusive scan
    for (int off = 1; off < T; off <<= 1) {
        int tmp = (t >= off) ? part[t - off] : 0;
        __syncthreads();
        part[t] += tmp;
        __syncthreads();
    }
    int run = part[t] - s;               // exclusive prefix
    for (int i = b; i < e; i++) {
        d_rowptr[i] = run;
        d_wp[i] = run;
        run += d_deg[i];
    }
    if (t == T - 1) d_rowptr[NN] = run;  // == EE
}

__global__ void k_fill(const int* __restrict__ ei) {
    int e = blockIdx.x * blockDim.x + threadIdx.x;
    if (e >= EE) return;
    int s = __ldg(ei + e), dt = __ldg(ei + EE + e);
    int p = atomicAdd(&d_wp[dt], 1);
    d_col[p] = s;
}

// ---------------- compute kernels ----------------

// h = relu(x @ Wp + bp)
__global__ void k_proj(const float* __restrict__ x,
                       const float* __restrict__ Wp,
                       const float* __restrict__ bp) {
    __shared__ float sW[FIN * DD];
    int d = threadIdx.x;  // 128 threads
    for (int i = d; i < FIN * DD; i += DD) sW[i] = Wp[i];
    float b = bp[d];
    __syncthreads();
    for (int n = blockIdx.x; n < NN; n += gridDim.x) {
        const float* xr = x + (size_t)n * FIN;
        float acc = b;
#pragma unroll
        for (int f = 0; f < FIN; f++)
            acc = fmaf(__ldg(xr + f), sW[f * DD + d], acc);
        d_h[n * DD + d] = fmaxf(acc, 0.f);
    }
}

// xh = A @ B where A = (fused ? relu(BN(d_acc)) : d_h). Epilogue fuses att dots.
// 128x128 C-tile, 256 threads, 8x8 register blocking.
__global__ void __launch_bounds__(256, 2) k_gemm(const float* __restrict__ B,
                                                 const float* __restrict__ asrcW,
                                                 const float* __restrict__ adstW,
                                                 int fused) {
    __shared__ float As[16][132];   // [k][m], padded
    __shared__ float Bs[16][128];   // [k][n]
    __shared__ float sa[DD], sd[DD], ssc[DD], ssh[DD];
    int tid = threadIdx.x;
    int tx = tid & 15, ty = tid >> 4;
    if (tid < DD) { sa[tid] = asrcW[tid]; ssc[tid] = d_bnsc[tid]; }
    else          { sd[tid - DD] = adstW[tid - DD]; ssh[tid - DD] = d_bnsh[tid - DD]; }
    __syncthreads();
    int row0 = blockIdx.x * 128;
    float acc[8][8];
#pragma unroll
    for (int i = 0; i < 8; i++)
#pragma unroll
        for (int j = 0; j < 8; j++) acc[i][j] = 0.f;

    for (int k0 = 0; k0 < 128; k0 += 16) {
#pragma unroll
        for (int i = 0; i < 8; i++) {
            int idx = tid + i * 256;
            int m = idx >> 4, k = idx & 15;
            int r = row0 + m;
            float v = 0.f;
            if (r < NN) {
                int c = k0 + k;
                if (fused) v = fmaxf(fmaf(d_acc[r * 128 + c], ssc[c], ssh[c]), 0.f);
                else       v = d_h[r * 128 + c];
            }
            As[k][m] = v;
        }
#pragma unroll
        for (int i = 0; i < 8; i++) {
            int idx = tid + i * 256;
            int k = idx >> 7, n2 = idx & 127;
            Bs[k][n2] = B[(k0 + k) * 128 + n2];
        }
        __syncthreads();
#pragma unroll
        for (int kk = 0; kk < 16; kk++) {
            float a[8], b[8];
#pragma unroll
            for (int i = 0; i < 8; i++) a[i] = As[kk][ty * 8 + i];
#pragma unroll
            for (int j = 0; j < 8; j++) b[j] = Bs[kk][tx * 8 + j];
#pragma unroll
            for (int i = 0; i < 8; i++)
#pragma unroll
                for (int j = 0; j < 8; j++)
                    acc[i][j] = fmaf(a[i], b[j], acc[i][j]);
        }
        __syncthreads();
    }

    // epilogue: write xh + fused attention dots
    int head = tx >> 1;            // 8 cols per thread => half a head
    int off  = head * 16 + (tx & 1) * 8;
#pragma unroll
    for (int i = 0; i < 8; i++) {
        int r = row0 + ty * 8 + i;
        float s = 0.f, dd2 = 0.f;
#pragma unroll
        for (int j = 0; j < 8; j++) {
            s   = fmaf(acc[i][j], sa[off + j], s);
            dd2 = fmaf(acc[i][j], sd[off + j], dd2);
        }
        s   += __shfl_xor_sync(0xffffffffu, s, 1);
        dd2 += __shfl_xor_sync(0xffffffffu, dd2, 1);
        if (r < NN) {
            float4* cp = (float4*)&d_xh[r * 128 + tx * 8];
            cp[0] = make_float4(acc[i][0], acc[i][1], acc[i][2], acc[i][3]);
            cp[1] = make_float4(acc[i][4], acc[i][5], acc[i][6], acc[i][7]);
            if ((tx & 1) == 0) {
                d_as[r * 8 + head] = s;
                d_ad[r * 8 + head] = dd2;
            }
        }
    }
}

// Fused attention: warp per dst node, single pass.
// Softmax shift = self-loop logit (shift-invariance; logits bounded -> no overflow).
// Unroll-by-4 prefetch of (col, a_src, feature row) to raise MLP.
__global__ void __launch_bounds__(256) k_agg() {
    __shared__ float ssum[DD], ssq[DD];
    int tid = threadIdx.x;
    if (tid < DD) { ssum[tid] = 0.f; ssq[tid] = 0.f; }
    __syncthreads();
    int lane = tid & 31;
    int h = lane >> 2;                 // head (4 lanes per head)
    int warp_g = blockIdx.x * (blockDim.x >> 5) + (tid >> 5);
    int nwarps = gridDim.x * (blockDim.x >> 5);
    float4 psum = make_float4(0.f, 0.f, 0.f, 0.f);
    float4 psq  = make_float4(0.f, 0.f, 0.f, 0.f);

    for (int n = warp_g; n < NN; n += nwarps) {
        float a_d   = __ldg(&d_ad[n * 8 + h]);
        float shift = lrelu(__ldg(&d_as[n * 8 + h]) + a_d);
        int beg = __ldg(&d_rowptr[n]), end = __ldg(&d_rowptr[n + 1]);
        // self loop: exp(0) = 1
        float den = 1.f;
        float4 acc = *(const float4*)&d_xh[n * 128 + lane * 4];

        for (int i = beg; i < end; i += 4) {
            int   c [4];
            float av[4];
            float4 xv[4];
#pragma unroll
            for (int j = 0; j < 4; j++)
                c[j] = (i + j < end) ? __ldg(&d_col[i + j]) : -1;
#pragma unroll
            for (int j = 0; j < 4; j++)
                av[j] = (c[j] >= 0) ? __ldg(&d_as[c[j] * 8 + h]) : 0.f;
#pragma unroll
            for (int j = 0; j < 4; j++) {
                int src = (c[j] >= 0) ? c[j] : n;
                xv[j] = *(const float4*)&d_xh[src * 128 + lane * 4];
            }
#pragma unroll
            for (int j = 0; j < 4; j++) {
                float ex = (c[j] >= 0) ? __expf(lrelu(av[j] + a_d) - shift) : 0.f;
                den += ex;
                acc.x = fmaf(ex, xv[j].x, acc.x);
                acc.y = fmaf(ex, xv[j].y, acc.y);
                acc.z = fmaf(ex, xv[j].z, acc.z);
                acc.w = fmaf(ex, xv[j].w, acc.w);
            }
        }
        float r = 1.f / den;
        float4 v = make_float4(acc.x * r, acc.y * r, acc.z * r, acc.w * r);
        *(float4*)&d_acc[n * 128 + lane * 4] = v;
        psum.x += v.x; psum.y += v.y; psum.z += v.z; psum.w += v.w;
        psq.x = fmaf(v.x, v.x, psq.x); psq.y = fmaf(v.y, v.y, psq.y);
        psq.z = fmaf(v.z, v.z, psq.z); psq.w = fmaf(v.w, v.w, psq.w);
    }
    // channel owned by lane: c = lane*4 + j
    int c = lane * 4;
    atomicAdd(&ssum[c + 0], psum.x); atomicAdd(&ssum[c + 1], psum.y);
    atomicAdd(&ssum[c + 2], psum.z); atomicAdd(&ssum[c + 3], psum.w);
    atomicAdd(&ssq [c + 0], psq.x);  atomicAdd(&ssq [c + 1], psq.y);
    atomicAdd(&ssq [c + 2], psq.z);  atomicAdd(&ssq [c + 3], psq.w);
    __syncthreads();
    if (tid < DD) {
        atomicAdd(&d_sum[tid], (double)ssum[tid]);
        atomicAdd(&d_sq[tid],  (double)ssq[tid]);
    }
}

// finalize BN scale/shift for this layer, reset stats for next layer
__global__ void k_bnfinal(const float* __restrict__ gamma,
                          const float* __restrict__ beta) {
    int d = threadIdx.x;  // 128 threads
    double mu = d_sum[d] / (double)NN;
    double var = d_sq[d] / (double)NN - mu * mu;
    float sc = gamma[d] * rsqrtf((float)var + BN_EPS);
    d_bnsc[d] = sc;
    d_bnsh[d] = beta[d] - (float)mu * sc;
    d_sum[d] = 0.0;
    d_sq[d] = 0.0;
}

// scatter nodes into per-graph sums, fusing the final BN+relu
__global__ void k_pool(const int* __restrict__ batch) {
    int i = blockIdx.x * blockDim.x + threadIdx.x;
    if (i >= NN * 32) return;
    int n = i >> 5, q = i & 31;
    int g = __ldg(batch + n);
    int c = q * 4;
    const float4 a = *(const float4*)&d_acc[n * 128 + c];
    float vx = fmaxf(fmaf(a.x, __ldg(&d_bnsc[c + 0]), __ldg(&d_bnsh[c + 0])), 0.f);
    float vy = fmaxf(fmaf(a.y, __ldg(&d_bnsc[c + 1]), __ldg(&d_bnsh[c + 1])), 0.f);
    float vz = fmaxf(fmaf(a.z, __ldg(&d_bnsc[c + 2]), __ldg(&d_bnsh[c + 2])), 0.f);
    float vw = fmaxf(fmaf(a.w, __ldg(&d_bnsc[c + 3]), __ldg(&d_bnsh[c + 3])), 0.f);
    red_add_v4(&d_pool[g * 128 + c], vx, vy, vz, vw);
    if (q == 0) atomicAdd(&d_cnt[g], 1.0f);
}

// output heads: relu(pooled @ W1 + b1) @ W2 + b2, per graph, 3 heads
__global__ void k_heads(const float* __restrict__ hW1, const float* __restrict__ hb1,
                        const float* __restrict__ hW2, const float* __restrict__ hb2,
                        float* __restrict__ outp) {
    int g = blockIdx.x;
    __shared__ float p[DD];
    __shared__ float red[2];
    int t = threadIdx.x;  // 64 threads
    float cnt = fmaxf(d_cnt[g], 1.0f);
    p[t]      = d_pool[g * 128 + t] / cnt;
    p[t + 64] = d_pool[g * 128 + 64 + t] / cnt;
    __syncthreads();
    for (int k = 0; k < 3; k++) {
        const float* W1 = hW1 + k * 128 * 64;
        float acc = hb1[k * 64 + t];
#pragma unroll 8
        for (int d2 = 0; d2 < 128; d2++)
            acc = fmaf(p[d2], W1[d2 * 64 + t], acc);
        acc = fmaxf(acc, 0.f) * hW2[k * 64 + t];
#pragma unroll
        for (int off = 16; off; off >>= 1)
            acc += __shfl_down_sync(0xffffffffu, acc, off);
        if ((t & 31) == 0) red[t >> 5] = acc;
        __syncthreads();
        if (t == 0) outp[g * 3 + k] = red[0] + red[1] + hb2[k];
        __syncthreads();
    }
}

// ---------------- launch ----------------
extern "C" void kernel_launch(void* const* d_in, const int* in_sizes, int n_in,
                              void* d_out, int out_size) {
    const float* x     = (const float*)d_in[0];
    const int*   ei    = (const int*)d_in[1];    // int32 (jax x64 disabled)
    const int*   batch = (const int*)d_in[2];
    const float* Wp    = (const float*)d_in[3];
    const float* bp    = (const float*)d_in[4];
    const float* Wg    = (const float*)d_in[5];
    const float* asrc  = (const float*)d_in[6];
    const float* adst  = (const float*)d_in[7];
    // d_in[8] = bg : GAT bias, exactly cancelled by the following BatchNorm
    const float* gamma = (const float*)d_in[9];
    const float* beta  = (const float*)d_in[10];
    const float* hW1   = (const float*)d_in[11];
    const float* hb1   = (const float*)d_in[12];
    const float* hW2   = (const float*)d_in[13];
    const float* hb2   = (const float*)d_in[14];
    float*       outp  = (float*)d_out;

    const int gemm_blocks = (NN + 127) / 128;        // 782
    const int e_blocks    = (EE + 255) / 256;        // 1172
    const int pool_blocks = (NN * 32 + 255) / 256;   // 12500

    // CSR build + zero init (edge list identical across layers)
    k_zero<<<512, 256>>>();
    k_hist<<<e_blocks, 256>>>(ei);
    k_scan<<<1, 1024>>>();
    k_fill<<<e_blocks, 256>>>(ei);

    k_proj<<<2048, 128>>>(x, Wp, bp);

    for (int l = 0; l < LL; l++) {
        const float* B = Wg + (size_t)l * DD * DD;
        k_gemm<<<gemm_blocks, 256>>>(B, asrc + l * HH * CC, adst + l * HH * CC, l > 0);
        k_agg<<<1536, 256>>>();
        k_bnfinal<<<1, 128>>>(gamma + l * DD, beta + l * DD);
    }

    k_pool<<<pool_blocks, 256>>>(batch);
    k_heads<<<GG, 64>>>(hW1, hb1, hW2, hb2, outp);
}

// round 17
// speedup vs baseline: 4.3987x; 1.0379x over previous
#include <cuda_runtime.h>
#include <cuda_bf16.h>
#include <math.h>

// ---------------- problem constants ----------------
#define NN   100000           // nodes
#define EE   300000           // directed edges
#define FIN  16
#define DD   128
#define HH   8
#define CC   16
#define LL   4
#define GG   1600
#define BN_EPS 1e-5f
#define NEG_SLOPE 0.2f

// ---------------- device scratch (no allocs allowed) ----------------
__device__ __align__(16) float d_h  [NN * DD];   // proj output (layer-0 GEMM input)
__device__ __align__(16) float d_xh [NN * DD];   // GAT linear output
__device__ __align__(16) float d_acc[NN * DD];   // softmax-normalized aggregation (pre-BN)
__device__ float  d_as [NN * HH];   // per-node att_src dots
__device__ float  d_ad [NN * HH];   // per-node att_dst dots
__device__ double d_sum[DD];        // BN sum
__device__ double d_sq [DD];        // BN sum of squares
__device__ float  d_bnsc[DD];       // BN scale  (gamma / sqrt(var+eps))
__device__ float  d_bnsh[DD];       // BN shift  (beta - mu*scale)
__device__ __align__(16) float d_pool[GG * DD];  // graph pooled sums
__device__ float  d_cnt [GG];       // nodes per graph
// CSR (dst-indexed, real edges only; self loops handled analytically)
__device__ int d_deg[NN];
__device__ int d_rowptr[NN + 1];
__device__ int d_wp[NN];
__device__ int d_col[EE];

// ---------------- helpers ----------------
__device__ __forceinline__ float lrelu(float v) {
    return v > 0.f ? v : NEG_SLOPE * v;
}
__device__ __forceinline__ void red_add_v4(float* addr, float a, float b, float c, float d) {
    asm volatile("red.global.add.v4.f32 [%0], {%1, %2, %3, %4};"
                 :: "l"(addr), "f"(a), "f"(b), "f"(c), "f"(d) : "memory");
}

// ---------------- CSR build (once per call) ----------------
__global__ void k_zero() {
    int i = blockIdx.x * blockDim.x + threadIdx.x;
    int st = gridDim.x * blockDim.x;
    for (int j = i; j < NN; j += st) d_deg[j] = 0;
    for (int j = i; j < GG * DD; j += st) d_pool[j] = 0.f;
    for (int j = i; j < GG; j += st) d_cnt[j] = 0.f;
    if (i < DD) { d_sum[i] = 0.0; d_sq[i] = 0.0; }
}

__global__ void k_hist(const int* __restrict__ ei) {
    int e = blockIdx.x * blockDim.x + threadIdx.x;
    if (e < EE) atomicAdd(&d_deg[__ldg(ei + EE + e)], 1);
}

// single-block exclusive scan over degrees -> rowptr and write-pointers
__global__ void k_scan() {
    __shared__ int part[1024];
    const int T = 1024;
    const int CH = (NN + T - 1) / T;     // 98
    int t = threadIdx.x;
    int b = t * CH;
    int e = min(b + CH, NN);
    int s = 0;
    for (int i = b; i < e; i++) s += d_deg[i];
    part[t] = s;
    __syncthreads();
    // Hillis-Steele inclusive scan
    for (int off = 1; off < T; off <<= 1) {
        int tmp = (t >= off) ? part[t - off] : 0;
        __syncthreads();
        part[t] += tmp;
        __syncthreads();
    }
    int run = part[t] - s;               // exclusive prefix
    for (int i = b; i < e; i++) {
        d_rowptr[i] = run;
        d_wp[i] = run;
        run += d_deg[i];
    }
    if (t == T - 1) d_rowptr[NN] = run;  // == EE
}

__global__ void k_fill(const int* __restrict__ ei) {
    int e = blockIdx.x * blockDim.x + threadIdx.x;
    if (e >= EE) return;
    int s = __ldg(ei + e), dt = __ldg(ei + EE + e);
    int p = atomicAdd(&d_wp[dt], 1);
    d_col[p] = s;
}

// ---------------- compute kernels ----------------

// h = relu(x @ Wp + bp)
__global__ void k_proj(const float* __restrict__ x,
                       const float* __restrict__ Wp,
                       const float* __restrict__ bp) {
    __shared__ float sW[FIN * DD];
    int d = threadIdx.x;  // 128 threads
    for (int i = d; i < FIN * DD; i += DD) sW[i] = Wp[i];
    float b = bp[d];
    __syncthreads();
    for (int n = blockIdx.x; n < NN; n += gridDim.x) {
        const float* xr = x + (size_t)n * FIN;
        float acc = b;
#pragma unroll
        for (int f = 0; f < FIN; f++)
            acc = fmaf(__ldg(xr + f), sW[f * DD + d], acc);
        d_h[n * DD + d] = fmaxf(acc, 0.f);
    }
}

// xh = A @ B where A = (fused ? relu(BN(d_acc)) : d_h). Epilogue fuses att dots.
// 128x128 C-tile, 256 threads, 8x8 register blocking.
__global__ void __launch_bounds__(256, 2) k_gemm(const float* __restrict__ B,
                                                 const float* __restrict__ asrcW,
                                                 const float* __restrict__ adstW,
                                                 int fused) {
    __shared__ float As[16][132];   // [k][m], padded
    __shared__ float Bs[16][128];   // [k][n]
    __shared__ float sa[DD], sd[DD], ssc[DD], ssh[DD];
    int tid = threadIdx.x;
    int tx = tid & 15, ty = tid >> 4;
    if (tid < DD) { sa[tid] = asrcW[tid]; ssc[tid] = d_bnsc[tid]; }
    else          { sd[tid - DD] = adstW[tid - DD]; ssh[tid - DD] = d_bnsh[tid - DD]; }
    __syncthreads();
    int row0 = blockIdx.x * 128;
    float acc[8][8];
#pragma unroll
    for (int i = 0; i < 8; i++)
#pragma unroll
        for (int j = 0; j < 8; j++) acc[i][j] = 0.f;

    for (int k0 = 0; k0 < 128; k0 += 16) {
#pragma unroll
        for (int i = 0; i < 8; i++) {
            int idx = tid + i * 256;
            int m = idx >> 4, k = idx & 15;
            int r = row0 + m;
            float v = 0.f;
            if (r < NN) {
                int c = k0 + k;
                if (fused) v = fmaxf(fmaf(d_acc[r * 128 + c], ssc[c], ssh[c]), 0.f);
                else       v = d_h[r * 128 + c];
            }
            As[k][m] = v;
        }
#pragma unroll
        for (int i = 0; i < 8; i++) {
            int idx = tid + i * 256;
            int k = idx >> 7, n2 = idx & 127;
            Bs[k][n2] = B[(k0 + k) * 128 + n2];
        }
        __syncthreads();
#pragma unroll
        for (int kk = 0; kk < 16; kk++) {
            float a[8], b[8];
#pragma unroll
            for (int i = 0; i < 8; i++) a[i] = As[kk][ty * 8 + i];
#pragma unroll
            for (int j = 0; j < 8; j++) b[j] = Bs[kk][tx * 8 + j];
#pragma unroll
            for (int i = 0; i < 8; i++)
#pragma unroll
                for (int j = 0; j < 8; j++)
                    acc[i][j] = fmaf(a[i], b[j], acc[i][j]);
        }
        __syncthreads();
    }

    // epilogue: write xh + fused attention dots
    int head = tx >> 1;            // 8 cols per thread => half a head
    int off  = head * 16 + (tx & 1) * 8;
#pragma unroll
    for (int i = 0; i < 8; i++) {
        int r = row0 + ty * 8 + i;
        float s = 0.f, dd2 = 0.f;
#pragma unroll
        for (int j = 0; j < 8; j++) {
            s   = fmaf(acc[i][j], sa[off + j], s);
            dd2 = fmaf(acc[i][j], sd[off + j], dd2);
        }
        s   += __shfl_xor_sync(0xffffffffu, s, 1);
        dd2 += __shfl_xor_sync(0xffffffffu, dd2, 1);
        if (r < NN) {
            float4* cp = (float4*)&d_xh[r * 128 + tx * 8];
            cp[0] = make_float4(acc[i][0], acc[i][1], acc[i][2], acc[i][3]);
            cp[1] = make_float4(acc[i][4], acc[i][5], acc[i][6], acc[i][7]);
            if ((tx & 1) == 0) {
                d_as[r * 8 + head] = s;
                d_ad[r * 8 + head] = dd2;
            }
        }
    }
}

// Fused attention: warp per dst node, single pass.
// Softmax shift = self-loop logit (shift-invariance; logits bounded -> no overflow).
// Unroll-by-4 prefetch of (col, a_src, feature row) to raise MLP.
__global__ void __launch_bounds__(256) k_agg() {
    __shared__ float ssum[DD], ssq[DD];
    int tid = threadIdx.x;
    if (tid < DD) { ssum[tid] = 0.f; ssq[tid] = 0.f; }
    __syncthreads();
    int lane = tid & 31;
    int h = lane >> 2;                 // head (4 lanes per head)
    int warp_g = blockIdx.x * (blockDim.x >> 5) + (tid >> 5);
    int nwarps = gridDim.x * (blockDim.x >> 5);
    float4 psum = make_float4(0.f, 0.f, 0.f, 0.f);
    float4 psq  = make_float4(0.f, 0.f, 0.f, 0.f);

    for (int n = warp_g; n < NN; n += nwarps) {
        float a_d   = __ldg(&d_ad[n * 8 + h]);
        float shift = lrelu(__ldg(&d_as[n * 8 + h]) + a_d);
        int beg = __ldg(&d_rowptr[n]), end = __ldg(&d_rowptr[n + 1]);
        // self loop: exp(0) = 1
        float den = 1.f;
        float4 acc = *(const float4*)&d_xh[n * 128 + lane * 4];

        for (int i = beg; i < end; i += 4) {
            int   c [4];
            float av[4];
            float4 xv[4];
#pragma unroll
            for (int j = 0; j < 4; j++)
                c[j] = (i + j < end) ? __ldg(&d_col[i + j]) : -1;
#pragma unroll
            for (int j = 0; j < 4; j++)
                av[j] = (c[j] >= 0) ? __ldg(&d_as[c[j] * 8 + h]) : 0.f;
#pragma unroll
            for (int j = 0; j < 4; j++) {
                int src = (c[j] >= 0) ? c[j] : n;
                xv[j] = *(const float4*)&d_xh[src * 128 + lane * 4];
            }
#pragma unroll
            for (int j = 0; j < 4; j++) {
                float ex = (c[j] >= 0) ? __expf(lrelu(av[j] + a_d) - shift) : 0.f;
                den += ex;
                acc.x = fmaf(ex, xv[j].x, acc.x);
                acc.y = fmaf(ex, xv[j].y, acc.y);
                acc.z = fmaf(ex, xv[j].z, acc.z);
                acc.w = fmaf(ex, xv[j].w, acc.w);
            }
        }
        float r = 1.f / den;
        float4 v = make_float4(acc.x * r, acc.y * r, acc.z * r, acc.w * r);
        *(float4*)&d_acc[n * 128 + lane * 4] = v;
        psum.x += v.x; psum.y += v.y; psum.z += v.z; psum.w += v.w;
        psq.x = fmaf(v.x, v.x, psq.x); psq.y = fmaf(v.y, v.y, psq.y);
        psq.z = fmaf(v.z, v.z, psq.z); psq.w = fmaf(v.w, v.w, psq.w);
    }
    // channel owned by lane: c = lane*4 + j
    int c = lane * 4;
    atomicAdd(&ssum[c + 0], psum.x); atomicAdd(&ssum[c + 1], psum.y);
    atomicAdd(&ssum[c + 2], psum.z); atomicAdd(&ssum[c + 3], psum.w);
    atomicAdd(&ssq [c + 0], psq.x);  atomicAdd(&ssq [c + 1], psq.y);
    atomicAdd(&ssq [c + 2], psq.z);  atomicAdd(&ssq [c + 3], psq.w);
    __syncthreads();
    if (tid < DD) {
        atomicAdd(&d_sum[tid], (double)ssum[tid]);
        atomicAdd(&d_sq[tid],  (double)ssq[tid]);
    }
}

// finalize BN scale/shift for this layer, reset stats for next layer
__global__ void k_bnfinal(const float* __restrict__ gamma,
                          const float* __restrict__ beta) {
    int d = threadIdx.x;  // 128 threads
    double mu = d_sum[d] / (double)NN;
    double var = d_sq[d] / (double)NN - mu * mu;
    float sc = gamma[d] * rsqrtf((float)var + BN_EPS);
    d_bnsc[d] = sc;
    d_bnsh[d] = beta[d] - (float)mu * sc;
    d_sum[d] = 0.0;
    d_sq[d] = 0.0;
}

// scatter nodes into per-graph sums, fusing the final BN+relu
__global__ void k_pool(const int* __restrict__ batch) {
    int i = blockIdx.x * blockDim.x + threadIdx.x;
    if (i >= NN * 32) return;
    int n = i >> 5, q = i & 31;
    int g = __ldg(batch + n);
    int c = q * 4;
    const float4 a = *(const float4*)&d_acc[n * 128 + c];
    float vx = fmaxf(fmaf(a.x, __ldg(&d_bnsc[c + 0]), __ldg(&d_bnsh[c + 0])), 0.f);
    float vy = fmaxf(fmaf(a.y, __ldg(&d_bnsc[c + 1]), __ldg(&d_bnsh[c + 1])), 0.f);
    float vz = fmaxf(fmaf(a.z, __ldg(&d_bnsc[c + 2]), __ldg(&d_bnsh[c + 2])), 0.f);
    float vw = fmaxf(fmaf(a.w, __ldg(&d_bnsc[c + 3]), __ldg(&d_bnsh[c + 3])), 0.f);
    red_add_v4(&d_pool[g * 128 + c], vx, vy, vz, vw);
    if (q == 0) atomicAdd(&d_cnt[g], 1.0f);
}

// output heads: relu(pooled @ W1 + b1) @ W2 + b2, per graph, 3 heads
__global__ void k_heads(const float* __restrict__ hW1, const float* __restrict__ hb1,
                        const float* __restrict__ hW2, const float* __restrict__ hb2,
                        float* __restrict__ outp) {
    int g = blockIdx.x;
    __shared__ float p[DD];
    __shared__ float red[2];
    int t = threadIdx.x;  // 64 threads
    float cnt = fmaxf(d_cnt[g], 1.0f);
    p[t]      = d_pool[g * 128 + t] / cnt;
    p[t + 64] = d_pool[g * 128 + 64 + t] / cnt;
    __syncthreads();
    for (int k = 0; k < 3; k++) {
        const float* W1 = hW1 + k * 128 * 64;
        float acc = hb1[k * 64 + t];
#pragma unroll 8
        for (int d2 = 0; d2 < 128; d2++)
            acc = fmaf(p[d2], W1[d2 * 64 + t], acc);
        acc = fmaxf(acc, 0.f) * hW2[k * 64 + t];
#pragma unroll
        for (int off = 16; off; off >>= 1)
            acc += __shfl_down_sync(0xffffffffu, acc, off);
        if ((t & 31) == 0) red[t >> 5] = acc;
        __syncthreads();
        if (t == 0) outp[g * 3 + k] = red[0] + red[1] + hb2[k];
        __syncthreads();
    }
}

// ---------------- launch ----------------
extern "C" void kernel_launch(void* const* d_in, const int* in_sizes, int n_in,
                              void* d_out, int out_size) {
    const float* x     = (const float*)d_in[0];
    const int*   ei    = (const int*)d_in[1];    // int32 (jax x64 disabled)
    const int*   batch = (const int*)d_in[2];
    const float* Wp    = (const float*)d_in[3];
    const float* bp    = (const float*)d_in[4];
    const float* Wg    = (const float*)d_in[5];
    const float* asrc  = (const float*)d_in[6];
    const float* adst  = (const float*)d_in[7];
    // d_in[8] = bg : GAT bias, exactly cancelled by the following BatchNorm
    const float* gamma = (const float*)d_in[9];
    const float* beta  = (const float*)d_in[10];
    const float* hW1   = (const float*)d_in[11];
    const float* hb1   = (const float*)d_in[12];
    const float* hW2   = (const float*)d_in[13];
    const float* hb2   = (const float*)d_in[14];
    float*       outp  = (float*)d_out;

    const int gemm_blocks = (NN + 127) / 128;        // 782
    const int e_blocks    = (EE + 255) / 256;        // 1172
    const int pool_blocks = (NN * 32 + 255) / 256;   // 12500

    // CSR build + zero init (edge list identical across layers)
    k_zero<<<512, 256>>>();
    k_hist<<<e_blocks, 256>>>(ei);
    k_scan<<<1, 1024>>>();
    k_fill<<<e_blocks, 256>>>(ei);

    k_proj<<<2048, 128>>>(x, Wp, bp);

    for (int l = 0; l < LL; l++) {
        const float* B = Wg + (size_t)l * DD * DD;
        k_gemm<<<gemm_blocks, 256>>>(B, asrc + l * HH * CC, adst + l * HH * CC, l > 0);
        k_agg<<<1536, 256>>>();
        k_bnfinal<<<1, 128>>>(gamma + l * DD, beta + l * DD);
    }

    k_pool<<<pool_blocks, 256>>>(batch);
    k_heads<<<GG, 64>>>(hW1, hb1, hW2, hb2, outp);
}